// round 15
// baseline (speedup 1.0000x reference)
#include <cuda_runtime.h>
#include <cuda_bf16.h>
#include <math.h>
#include <stdint.h>

#define DD 1024
#define NE 100
#define BT 32768   // 8*4096

// ---------------- device scratch ----------------
__device__ __nv_bfloat16 g_cn_hi[128 * DD];          // normalized centroids bf16 hi (padded)
__device__ __nv_bfloat16 g_cn_lo[128 * DD];          // normalized centroids bf16 lo
__device__ __nv_bfloat16 g_ah[(size_t)128 * BT];     // assignment^T bf16 hi [e][t]
__device__ __nv_bfloat16 g_al[(size_t)128 * BT];     // assignment^T bf16 lo [e][t]
__device__ float g_wpart[256 * 128];                 // per-block weight partials
__device__ float g_efpart[(size_t)4 * 8 * 128 * DD]; // split-K=4 partials

// ---------------- helpers ----------------
__device__ __forceinline__ uint32_t smem_u32(const void* p) {
    uint32_t a;
    asm("{ .reg .u64 t; cvta.to.shared.u64 t, %1; cvt.u32.u64 %0, t; }" : "=r"(a) : "l"(p));
    return a;
}
__device__ __forceinline__ uint32_t sw128(uint32_t off) {
    return off ^ ((off >> 3) & 0x70u);
}
__device__ __forceinline__ uint32_t pk_bf16(float lo, float hi) {
    uint32_t r;
    asm("cvt.rn.bf16x2.f32 %0, %1, %2;" : "=r"(r) : "f"(hi), "f"(lo));
    return r;
}
__device__ __forceinline__ void sts64(uint32_t addr, uint32_t a, uint32_t b) {
    asm volatile("st.shared.v2.b32 [%0], {%1, %2};" :: "r"(addr), "r"(a), "r"(b) : "memory");
}
__device__ __forceinline__ void sts128(uint32_t addr, uint4 v) {
    asm volatile("st.shared.v4.b32 [%0], {%1, %2, %3, %4};"
                 :: "r"(addr), "r"(v.x), "r"(v.y), "r"(v.z), "r"(v.w) : "memory");
}
__device__ __forceinline__ void ldm4(uint32_t addr, uint32_t* r) {
    asm volatile("ldmatrix.sync.aligned.m8n8.x4.shared.b16 {%0,%1,%2,%3}, [%4];"
                 : "=r"(r[0]), "=r"(r[1]), "=r"(r[2]), "=r"(r[3]) : "r"(addr));
}
__device__ __forceinline__ void ldm4t(uint32_t addr, uint32_t* r) {
    asm volatile("ldmatrix.sync.aligned.m8n8.x4.trans.shared.b16 {%0,%1,%2,%3}, [%4];"
                 : "=r"(r[0]), "=r"(r[1]), "=r"(r[2]), "=r"(r[3]) : "r"(addr));
}
__device__ __forceinline__ void mmabf(float* c, const uint32_t* a, uint32_t b0, uint32_t b1) {
    asm volatile("mma.sync.aligned.m16n8k16.row.col.f32.bf16.bf16.f32 "
                 "{%0,%1,%2,%3}, {%4,%5,%6,%7}, {%8,%9}, {%0,%1,%2,%3};"
                 : "+f"(c[0]), "+f"(c[1]), "+f"(c[2]), "+f"(c[3])
                 : "r"(a[0]), "r"(a[1]), "r"(a[2]), "r"(a[3]), "r"(b0), "r"(b1));
}

// ---------------- kernel 0: normalize centroids -> bf16 hi/lo, zero-pad ----------------
__global__ void __launch_bounds__(256) k_cnorm(const float* __restrict__ cent) {
    int e = blockIdx.x;
    int tid = threadIdx.x;
    uint2* dh = (uint2*)(g_cn_hi + (size_t)e * DD);
    uint2* dl = (uint2*)(g_cn_lo + (size_t)e * DD);
    if (e >= NE) { dh[tid] = make_uint2(0u, 0u); dl[tid] = make_uint2(0u, 0u); return; }
    __shared__ float warps[8];
    float4 a = ((const float4*)(cent + (size_t)e * DD))[tid];
    float ss = a.x * a.x + a.y * a.y + a.z * a.z + a.w * a.w;
#pragma unroll
    for (int m = 16; m; m >>= 1) ss += __shfl_xor_sync(0xffffffffu, ss, m);
    if ((tid & 31) == 0) warps[tid >> 5] = ss;
    __syncthreads();
    float tot = 0.f;
#pragma unroll
    for (int w = 0; w < 8; ++w) tot += warps[w];
    float inv = 1.0f / fmaxf(sqrtf(tot), 1e-12f);
    float4 v = make_float4(a.x * inv, a.y * inv, a.z * inv, a.w * inv);
    float h0 = __bfloat162float(__float2bfloat16_rn(v.x));
    float h1 = __bfloat162float(__float2bfloat16_rn(v.y));
    float h2 = __bfloat162float(__float2bfloat16_rn(v.z));
    float h3 = __bfloat162float(__float2bfloat16_rn(v.w));
    dh[tid] = make_uint2(pk_bf16(h0, h1), pk_bf16(h2, h3));
    dl[tid] = make_uint2(pk_bf16(v.x - h0, v.y - h1), pk_bf16(v.z - h2, v.w - h3));
}

// MMA phase: 32x64 warp tile, k=64 chunk. Buffers: Ah at cb, Al +16K, Bh +32K, Bl +48K.
// B fragments double-buffered across np: LDSM for np+1 issued before the 12 MMAs of np,
// giving ~48 issue-cycles of LDSM->use distance. 12 HMMAs per np stay term-major
// (accumulator reuse at dependency distance 4).
#define MMA_PHASE(cb, LDMB)                                                                 \
    do {                                                                                    \
        uint32_t tAh = (cb), tAl = (cb) + 16384u, tBh = (cb) + 32768u, tBl = (cb) + 49152u; \
        uint32_t koff = (uint32_t)((lane >> 4) & 1) * 16u;                                  \
        _Pragma("unroll")                                                                   \
        for (int ks = 0; ks < 4; ++ks) {                                                    \
            uint32_t kb = (uint32_t)ks * 32u;                                               \
            uint32_t ah[2][4], al[2][4];                                                    \
            _Pragma("unroll")                                                               \
            for (int mt = 0; mt < 2; ++mt) {                                                \
                uint32_t off = sw128((uint32_t)((m0 + mt * 16 + (lane & 15)) * 128) + kb + koff); \
                ldm4(tAh + off, ah[mt]);                                                    \
                ldm4(tAl + off, al[mt]);                                                    \
            }                                                                               \
            uint32_t bh[2][4], bl[2][4];                                                    \
            LDMB(0, bh[0], bl[0]);                                                          \
            _Pragma("unroll")                                                               \
            for (int np = 0; np < 4; ++np) {                                                \
                const int cur = np & 1;                                                     \
                if (np < 3) { LDMB(np + 1, bh[cur ^ 1], bl[cur ^ 1]); }                     \
                mmabf(acc[0][np * 2],     ah[0], bh[cur][0], bh[cur][2]);                   \
                mmabf(acc[1][np * 2],     ah[1], bh[cur][0], bh[cur][2]);                   \
                mmabf(acc[0][np * 2 + 1], ah[0], bh[cur][1], bh[cur][3]);                   \
                mmabf(acc[1][np * 2 + 1], ah[1], bh[cur][1], bh[cur][3]);                   \
                mmabf(acc[0][np * 2],     ah[0], bl[cur][0], bl[cur][2]);                   \
                mmabf(acc[1][np * 2],     ah[1], bl[cur][0], bl[cur][2]);                   \
                mmabf(acc[0][np * 2 + 1], ah[0], bl[cur][1], bl[cur][3]);                   \
                mmabf(acc[1][np * 2 + 1], ah[1], bl[cur][1], bl[cur][3]);                   \
                mmabf(acc[0][np * 2],     al[0], bh[cur][0], bh[cur][2]);                   \
                mmabf(acc[1][np * 2],     al[1], bh[cur][0], bh[cur][2]);                   \
                mmabf(acc[0][np * 2 + 1], al[0], bh[cur][1], bh[cur][3]);                   \
                mmabf(acc[1][np * 2 + 1], al[1], bh[cur][1], bh[cur][3]);                   \
            }                                                                               \
        }                                                                                   \
    } while (0)

// ---------------- kernel 1: sim GEMM (HMMA hi/lo, double-buffered) + softmax ----------
#define SIM_SMEM (1024 + 1024 + 2 * 65536)
#define SPITCH 130

__global__ void __launch_bounds__(256, 1) k_sim(const float* __restrict__ tokens,
                                                float* __restrict__ aout) {
    extern __shared__ char dsm[];
    uint32_t raw = smem_u32(dsm);
    uint32_t base = (raw + 1023u) & ~1023u;
    char* cbase = dsm + (base - raw);
    float* snorm = (float*)cbase;               // 128 f32
    float* stage = (float*)(cbase + 1024);      // epilogue staging (aliases tile bufs)
    uint32_t tiles = base + 1024u;

    int tid = threadIdx.x;
    int lane = tid & 31, w = tid >> 5;
    int wm = w & 3, wn = w >> 2;
    int m0 = wm * 32, n0 = wn * 64;
    size_t row0 = (size_t)blockIdx.x << 7;

    const int ty16 = tid >> 4, tx = tid & 15;
    const int brow = tid >> 3, q = tid & 7;
    const float* Abase = tokens + row0 * DD;

    float acc[2][8][4];
#pragma unroll
    for (int i = 0; i < 2; ++i)
#pragma unroll
        for (int j = 0; j < 8; ++j)
#pragma unroll
            for (int p = 0; p < 4; ++p) acc[i][j][p] = 0.f;
    float ss[8];
#pragma unroll
    for (int g = 0; g < 8; ++g) ss[g] = 0.f;

    float4 pa[8];
    uint4 pbh[4], pbl[4];

#define SIM_LOAD(c)                                                                         \
    do {                                                                                    \
        _Pragma("unroll")                                                                   \
        for (int g = 0; g < 8; ++g)                                                         \
            pa[g] = *(const float4*)(Abase + (size_t)(g * 16 + ty16) * DD + (c) * 64 + tx * 4); \
        _Pragma("unroll")                                                                   \
        for (int p = 0; p < 4; ++p) {                                                       \
            int r = p * 32 + brow;                                                          \
            pbh[p] = *(const uint4*)(g_cn_hi + (size_t)r * DD + (c) * 64 + q * 8);          \
            pbl[p] = *(const uint4*)(g_cn_lo + (size_t)r * DD + (c) * 64 + q * 8);          \
        }                                                                                   \
    } while (0)

#define SIM_STORE(tb)                                                                       \
    do {                                                                                    \
        uint32_t sAh = (tb), sAl = (tb) + 16384u, sBh = (tb) + 32768u, sBl = (tb) + 49152u; \
        _Pragma("unroll")                                                                   \
        for (int g = 0; g < 8; ++g) {                                                       \
            float4 a = pa[g];                                                               \
            ss[g] += a.x * a.x + a.y * a.y + a.z * a.z + a.w * a.w;                         \
            float h0 = __bfloat162float(__float2bfloat16_rn(a.x));                          \
            float h1 = __bfloat162float(__float2bfloat16_rn(a.y));                          \
            float h2 = __bfloat162float(__float2bfloat16_rn(a.z));                          \
            float h3 = __bfloat162float(__float2bfloat16_rn(a.w));                          \
            uint32_t off = sw128((uint32_t)((g * 16 + ty16) * 128 + tx * 8));               \
            sts64(sAh + off, pk_bf16(h0, h1), pk_bf16(h2, h3));                             \
            sts64(sAl + off, pk_bf16(a.x - h0, a.y - h1), pk_bf16(a.z - h2, a.w - h3));     \
        }                                                                                   \
        _Pragma("unroll")                                                                   \
        for (int p = 0; p < 4; ++p) {                                                       \
            int r = p * 32 + brow;                                                          \
            uint32_t off = sw128((uint32_t)(r * 128 + q * 16));                             \
            sts128(sBh + off, pbh[p]);                                                      \
            sts128(sBl + off, pbl[p]);                                                      \
        }                                                                                   \
    } while (0)

#define SIM_LDMB(NP, BH, BL)                                                                \
    do {                                                                                    \
        uint32_t boff = sw128((uint32_t)((n0 + (NP) * 16 + (lane & 15)) * 128) + kb + koff);\
        ldm4(tBh + boff, BH);                                                               \
        ldm4(tBl + boff, BL);                                                               \
    } while (0)

    SIM_LOAD(0);
    SIM_STORE(tiles);
    __syncthreads();
    SIM_LOAD(1);

    for (int c = 0; c < 16; ++c) {
        uint32_t cb = tiles + (uint32_t)(c & 1) * 65536u;
        uint32_t nb = tiles + (uint32_t)((c + 1) & 1) * 65536u;
        if (c < 15) SIM_STORE(nb);
        MMA_PHASE(cb, SIM_LDMB);
        __syncthreads();
        if (c < 14) SIM_LOAD(c + 2);
    }

    // token norms
#pragma unroll
    for (int g = 0; g < 8; ++g) {
        float s = ss[g];
        s += __shfl_xor_sync(0xffffffffu, s, 1);
        s += __shfl_xor_sync(0xffffffffu, s, 2);
        s += __shfl_xor_sync(0xffffffffu, s, 4);
        s += __shfl_xor_sync(0xffffffffu, s, 8);
        if (tx == 0) snorm[g * 16 + ty16] = s;
    }
    __syncthreads();   // all ldmatrix done before staging overwrites buffers

    // stage sim tile to smem (pitch SPITCH)
#pragma unroll
    for (int mt = 0; mt < 2; ++mt)
#pragma unroll
        for (int nt = 0; nt < 8; ++nt) {
            int r = m0 + mt * 16 + (lane >> 2);
            int col = n0 + nt * 8 + (lane & 3) * 2;
            *(float2*)&stage[r * SPITCH + col] = make_float2(acc[mt][nt][0], acc[mt][nt][1]);
            *(float2*)&stage[(r + 8) * SPITCH + col] = make_float2(acc[mt][nt][2], acc[mt][nt][3]);
        }
    __syncthreads();

    if (tid < 128) {
        float v[128];
#pragma unroll
        for (int j = 0; j < 128; ++j) v[j] = stage[tid * SPITCH + j];
        float sc = 10.0f / fmaxf(sqrtf(snorm[tid]), 1e-12f);  // (1/T)/max(||x||,eps)
        float mx = -1e30f;
#pragma unroll
        for (int j = 0; j < NE; ++j) { v[j] *= sc; mx = fmaxf(mx, v[j]); }
        float sum = 0.f;
#pragma unroll
        for (int j = 0; j < 128; ++j) {
            float t = (j < NE) ? __expf(v[j] - mx) : 0.f;
            v[j] = t;
            sum += t;
        }
        float inv = 1.0f / sum;
#pragma unroll
        for (int j = 0; j < 128; ++j) v[j] *= inv;

        size_t trow = row0 + tid;
        float* rp = aout + trow * NE;
#pragma unroll
        for (int j = 0; j < 25; ++j)
            *(float4*)(rp + j * 4) = make_float4(v[j * 4], v[j * 4 + 1], v[j * 4 + 2], v[j * 4 + 3]);
        // assignment^T bf16 hi/lo for GEMM2 (warp-coalesced: lanes span consecutive tokens)
#pragma unroll
        for (int e = 0; e < 128; ++e) {
            __nv_bfloat16 hb = __float2bfloat16_rn(v[e]);
            g_ah[(size_t)e * BT + trow] = hb;
            g_al[(size_t)e * BT + trow] = __float2bfloat16_rn(v[e] - __bfloat162float(hb));
        }
        // write back for weight column sums
#pragma unroll
        for (int j = 0; j < 128; ++j) stage[tid * SPITCH + j] = v[j];
    }
    __syncthreads();
    if (tid < 128) {
        float s = 0.f;
#pragma unroll
        for (int r = 0; r < 128; ++r) s += stage[r * SPITCH + tid];
        g_wpart[blockIdx.x * 128 + tid] = s;
    }
}

// ---------------- kernel 3: entity_features GEMM (HMMA, split-K=4, 2 CTA/SM) ----------
#define EF_SMEM (1024 + 65536)

__global__ void __launch_bounds__(256, 2) k_ef(const float* __restrict__ tokens) {
    extern __shared__ char dsm[];
    uint32_t raw = smem_u32(dsm);
    uint32_t tiles = (raw + 1023u) & ~1023u;

    int tid = threadIdx.x;
    int lane = tid & 31, w = tid >> 5;
    int wm = w & 3, wn = w >> 2;
    int m0 = wm * 32, n0 = wn * 64;

    int bid = blockIdx.x;
    int dt = bid & 7;
    int b  = (bid >> 3) & 7;
    int s  = bid >> 6;             // 0..3
    size_t tok0 = (size_t)b * 4096 + (size_t)s * 1024;

    const int ty16 = tid >> 4, tx = tid & 15;
    const int brow = tid >> 3, q = tid & 7;

    float acc[2][8][4];
#pragma unroll
    for (int i = 0; i < 2; ++i)
#pragma unroll
        for (int j = 0; j < 8; ++j)
#pragma unroll
            for (int p = 0; p < 4; ++p) acc[i][j][p] = 0.f;

    uint32_t krow = (uint32_t)((lane & 7) + ((lane >> 4) & 1) * 8);
    uint32_t dh16 = (uint32_t)((lane >> 3) & 1) * 16u;
    uint32_t bsub = (uint32_t)wn * 8192u;

#define EF_LDMB(NP, BH, BL)                                                                 \
    do {                                                                                    \
        uint32_t boff = bsub + sw128((uint32_t)((ks * 16 + krow) * 128 + (NP) * 32) + dh16);\
        ldm4t(tBh + boff, BH);                                                              \
        ldm4t(tBl + boff, BL);                                                              \
    } while (0)

    for (int c = 0; c < 16; ++c) {
        uint32_t sAh = tiles, sAl = tiles + 16384u, sBh = tiles + 32768u, sBl = tiles + 49152u;
        // A: assignment^T bf16 hi/lo [e][t]
#pragma unroll
        for (int p = 0; p < 4; ++p) {
            int r = p * 32 + brow;
            uint32_t off = sw128((uint32_t)(r * 128 + q * 16));
            sts128(sAh + off, *(const uint4*)(g_ah + (size_t)r * BT + tok0 + c * 64 + q * 8));
            sts128(sAl + off, *(const uint4*)(g_al + (size_t)r * BT + tok0 + c * 64 + q * 8));
        }
        // B: tokens fp32 -> bf16 hi/lo, two 64x64 subtiles [k][d]
#pragma unroll
        for (int g = 0; g < 4; ++g)
#pragma unroll
            for (int sub = 0; sub < 2; ++sub) {
                float4 a = *(const float4*)(tokens + (tok0 + c * 64 + g * 16 + ty16) * DD +
                                            dt * 128 + sub * 64 + tx * 4);
                float h0 = __bfloat162float(__float2bfloat16_rn(a.x));
                float h1 = __bfloat162float(__float2bfloat16_rn(a.y));
                float h2 = __bfloat162float(__float2bfloat16_rn(a.z));
                float h3 = __bfloat162float(__float2bfloat16_rn(a.w));
                uint32_t off = (uint32_t)sub * 8192u +
                               sw128((uint32_t)((g * 16 + ty16) * 128 + tx * 8));
                sts64(sBh + off, pk_bf16(h0, h1), pk_bf16(h2, h3));
                sts64(sBl + off, pk_bf16(a.x - h0, a.y - h1), pk_bf16(a.z - h2, a.w - h3));
            }
        __syncthreads();
        MMA_PHASE(tiles, EF_LDMB);
        __syncthreads();
    }

    float* ob = g_efpart + ((size_t)(s * 8 + b) * 128) * DD + (size_t)dt * 128;
#pragma unroll
    for (int mt = 0; mt < 2; ++mt)
#pragma unroll
        for (int nt = 0; nt < 8; ++nt) {
            int e = m0 + mt * 16 + (lane >> 2);
            int d = n0 + nt * 8 + (lane & 3) * 2;
            *(float2*)(ob + (size_t)e * DD + d) = make_float2(acc[mt][nt][0], acc[mt][nt][1]);
            *(float2*)(ob + (size_t)(e + 8) * DD + d) = make_float2(acc[mt][nt][2], acc[mt][nt][3]);
        }
}

// ---------------- kernel 4: combine 4 splits + inline weight reduce + divide ----------
__global__ void __launch_bounds__(256) k_combine(float* __restrict__ efout) {
    __shared__ float wsh;
    int be = blockIdx.x;           // b*100 + e
    int e = be % 100;
    int b = be / 100;
    int tid = threadIdx.x;

    if (tid < 32) {
        float s = g_wpart[(b * 32 + tid) * 128 + e];
#pragma unroll
        for (int m = 16; m; m >>= 1) s += __shfl_xor_sync(0xffffffffu, s, m);
        if (tid == 0) wsh = s + 1e-6f;
    }
    __syncthreads();
    float inv = 1.0f / wsh;

    int d4 = tid;
    const float4* p = (const float4*)g_efpart;
    size_t idx = ((size_t)b * 128 + e) * 256 + d4;
    size_t sstr = (size_t)8 * 128 * 256;
    float4 v = p[idx];
    float4 t;
    t = p[idx + sstr];     v.x += t.x; v.y += t.y; v.z += t.z; v.w += t.w;
    t = p[idx + 2 * sstr]; v.x += t.x; v.y += t.y; v.z += t.z; v.w += t.w;
    t = p[idx + 3 * sstr]; v.x += t.x; v.y += t.y; v.z += t.z; v.w += t.w;
    ((float4*)efout)[(size_t)be * 256 + d4] =
        make_float4(v.x * inv, v.y * inv, v.z * inv, v.w * inv);
}

extern "C" void kernel_launch(void* const* d_in, const int* in_sizes, int n_in,
                              void* d_out, int out_size) {
    const float* tokens = (const float*)d_in[0];   // (8,4096,1024)
    const float* cent   = (const float*)d_in[1];   // (100,1024)
    float* out = (float*)d_out;                    // assignment | entity_features

    cudaFuncSetAttribute(k_sim, cudaFuncAttributeMaxDynamicSharedMemorySize, SIM_SMEM);
    cudaFuncSetAttribute(k_ef,  cudaFuncAttributeMaxDynamicSharedMemorySize, EF_SMEM);

    k_cnorm<<<128, 256>>>(cent);
    k_sim<<<256, 256, SIM_SMEM>>>(tokens, out);
    k_ef<<<256, 256, EF_SMEM>>>(tokens);
    k_combine<<<800, 256>>>(out + (size_t)BT * NE);
}

// round 16
// speedup vs baseline: 1.4158x; 1.4158x over previous
#include <cuda_runtime.h>
#include <cuda_fp16.h>
#include <math.h>
#include <stdint.h>

#define DD 1024
#define NE 100
#define BT 32768   // 8*4096

// ---------------- device scratch ----------------
__device__ __half g_cn[128 * DD];                    // normalized centroids fp16 (padded)
__device__ __half g_th_a[(size_t)128 * BT];          // assignment^T fp16 [e][t]
__device__ float g_wpart[256 * 128];                 // per-block weight partials
__device__ float g_efpart[(size_t)4 * 8 * 128 * DD]; // split-K=4 partials

// ---------------- helpers ----------------
__device__ __forceinline__ uint32_t smem_u32(const void* p) {
    uint32_t a;
    asm("{ .reg .u64 t; cvta.to.shared.u64 t, %1; cvt.u32.u64 %0, t; }" : "=r"(a) : "l"(p));
    return a;
}
__device__ __forceinline__ uint32_t sw128(uint32_t off) {
    return off ^ ((off >> 3) & 0x70u);
}
__device__ __forceinline__ uint32_t pk_f16(float lo, float hi) {
    uint32_t r;
    asm("cvt.rn.f16x2.f32 %0, %1, %2;" : "=r"(r) : "f"(hi), "f"(lo));
    return r;
}
__device__ __forceinline__ void sts64(uint32_t addr, uint32_t a, uint32_t b) {
    asm volatile("st.shared.v2.b32 [%0], {%1, %2};" :: "r"(addr), "r"(a), "r"(b) : "memory");
}
__device__ __forceinline__ void sts128(uint32_t addr, uint4 v) {
    asm volatile("st.shared.v4.b32 [%0], {%1, %2, %3, %4};"
                 :: "r"(addr), "r"(v.x), "r"(v.y), "r"(v.z), "r"(v.w) : "memory");
}
__device__ __forceinline__ void ldm4(uint32_t addr, uint32_t* r) {
    asm volatile("ldmatrix.sync.aligned.m8n8.x4.shared.b16 {%0,%1,%2,%3}, [%4];"
                 : "=r"(r[0]), "=r"(r[1]), "=r"(r[2]), "=r"(r[3]) : "r"(addr));
}
__device__ __forceinline__ void ldm4t(uint32_t addr, uint32_t* r) {
    asm volatile("ldmatrix.sync.aligned.m8n8.x4.trans.shared.b16 {%0,%1,%2,%3}, [%4];"
                 : "=r"(r[0]), "=r"(r[1]), "=r"(r[2]), "=r"(r[3]) : "r"(addr));
}
__device__ __forceinline__ void mmaf16(float* c, const uint32_t* a, uint32_t b0, uint32_t b1) {
    asm volatile("mma.sync.aligned.m16n8k16.row.col.f32.f16.f16.f32 "
                 "{%0,%1,%2,%3}, {%4,%5,%6,%7}, {%8,%9}, {%0,%1,%2,%3};"
                 : "+f"(c[0]), "+f"(c[1]), "+f"(c[2]), "+f"(c[3])
                 : "r"(a[0]), "r"(a[1]), "r"(a[2]), "r"(a[3]), "r"(b0), "r"(b1));
}

// ---------------- kernel 0: normalize centroids -> fp16, zero-pad ----------------
__global__ void __launch_bounds__(256) k_cnorm(const float* __restrict__ cent) {
    int e = blockIdx.x;
    int tid = threadIdx.x;
    uint2* dh = (uint2*)(g_cn + (size_t)e * DD);
    if (e >= NE) { dh[tid] = make_uint2(0u, 0u); return; }
    __shared__ float warps[8];
    float4 a = ((const float4*)(cent + (size_t)e * DD))[tid];
    float ss = a.x * a.x + a.y * a.y + a.z * a.z + a.w * a.w;
#pragma unroll
    for (int m = 16; m; m >>= 1) ss += __shfl_xor_sync(0xffffffffu, ss, m);
    if ((tid & 31) == 0) warps[tid >> 5] = ss;
    __syncthreads();
    float tot = 0.f;
#pragma unroll
    for (int w = 0; w < 8; ++w) tot += warps[w];
    float inv = 1.0f / fmaxf(sqrtf(tot), 1e-12f);
    dh[tid] = make_uint2(pk_f16(a.x * inv, a.y * inv), pk_f16(a.z * inv, a.w * inv));
}

// ---------------- kernel 1: sim GEMM (fp16: tokens hi/lo x centroids) + softmax -------
// Buffers per chunk: tAh (tokens hi, 16K), tAl (tokens lo, 16K), tB (centroids, 16K) = 48K.
// Double-buffered (2x48K) at 1 CTA/SM; epilogue stage aliases buffer region.
#define SIM_SMEM (1024 + 1024 + 2 * 49152)
#define SPITCH 130

__global__ void __launch_bounds__(256, 1) k_sim(const float* __restrict__ tokens,
                                                float* __restrict__ aout) {
    extern __shared__ char dsm[];
    uint32_t raw = smem_u32(dsm);
    uint32_t base = (raw + 1023u) & ~1023u;
    char* cbase = dsm + (base - raw);
    float* snorm = (float*)cbase;               // 128 f32
    float* stage = (float*)(cbase + 1024);      // epilogue staging (aliases tile bufs)
    uint32_t tiles = base + 1024u;

    int tid = threadIdx.x;
    int lane = tid & 31, w = tid >> 5;
    int wm = w & 3, wn = w >> 2;
    int m0 = wm * 32, n0 = wn * 64;
    size_t row0 = (size_t)blockIdx.x << 7;

    const int ty16 = tid >> 4, tx = tid & 15;
    const int brow = tid >> 3, q = tid & 7;
    const float* Abase = tokens + row0 * DD;

    float acc[2][8][4];
#pragma unroll
    for (int i = 0; i < 2; ++i)
#pragma unroll
        for (int j = 0; j < 8; ++j)
#pragma unroll
            for (int p = 0; p < 4; ++p) acc[i][j][p] = 0.f;
    float ss[8];
#pragma unroll
    for (int g = 0; g < 8; ++g) ss[g] = 0.f;

    float4 pa[8];
    uint4 pb[4];

#define SIM_LOAD(c)                                                                         \
    do {                                                                                    \
        _Pragma("unroll")                                                                   \
        for (int g = 0; g < 8; ++g)                                                         \
            pa[g] = *(const float4*)(Abase + (size_t)(g * 16 + ty16) * DD + (c) * 64 + tx * 4); \
        _Pragma("unroll")                                                                   \
        for (int p = 0; p < 4; ++p) {                                                       \
            int r = p * 32 + brow;                                                          \
            pb[p] = *(const uint4*)(g_cn + (size_t)r * DD + (c) * 64 + q * 8);              \
        }                                                                                   \
    } while (0)

#define SIM_STORE(tb)                                                                       \
    do {                                                                                    \
        uint32_t sAh = (tb), sAl = (tb) + 16384u, sB = (tb) + 32768u;                       \
        _Pragma("unroll")                                                                   \
        for (int g = 0; g < 8; ++g) {                                                       \
            float4 a = pa[g];                                                               \
            ss[g] += a.x * a.x + a.y * a.y + a.z * a.z + a.w * a.w;                         \
            float h0 = __half2float(__float2half_rn(a.x));                                  \
            float h1 = __half2float(__float2half_rn(a.y));                                  \
            float h2 = __half2float(__float2half_rn(a.z));                                  \
            float h3 = __half2float(__float2half_rn(a.w));                                  \
            uint32_t off = sw128((uint32_t)((g * 16 + ty16) * 128 + tx * 8));               \
            sts64(sAh + off, pk_f16(h0, h1), pk_f16(h2, h3));                               \
            sts64(sAl + off, pk_f16(a.x - h0, a.y - h1), pk_f16(a.z - h2, a.w - h3));       \
        }                                                                                   \
        _Pragma("unroll")                                                                   \
        for (int p = 0; p < 4; ++p) {                                                       \
            int r = p * 32 + brow;                                                          \
            uint32_t off = sw128((uint32_t)(r * 128 + q * 16));                             \
            sts128(sB + off, pb[p]);                                                        \
        }                                                                                   \
    } while (0)

    SIM_LOAD(0);
    SIM_STORE(tiles);
    __syncthreads();
    SIM_LOAD(1);

    for (int c = 0; c < 16; ++c) {
        uint32_t cb = tiles + (uint32_t)(c & 1) * 49152u;
        uint32_t nb = tiles + (uint32_t)((c + 1) & 1) * 49152u;
        if (c < 15) SIM_STORE(nb);
        // MMA phase: 2 terms (th*c, tl*c), 8 HMMAs per (ks,np), acc reuse distance 4
        {
            uint32_t tAh = cb, tAl = cb + 16384u, tB = cb + 32768u;
            uint32_t koff = (uint32_t)((lane >> 4) & 1) * 16u;
#pragma unroll
            for (int ks = 0; ks < 4; ++ks) {
                uint32_t kb = (uint32_t)ks * 32u;
                uint32_t ah[2][4], al[2][4];
#pragma unroll
                for (int mt = 0; mt < 2; ++mt) {
                    uint32_t off = sw128((uint32_t)((m0 + mt * 16 + (lane & 15)) * 128) + kb + koff);
                    ldm4(tAh + off, ah[mt]);
                    ldm4(tAl + off, al[mt]);
                }
#pragma unroll
                for (int np = 0; np < 4; ++np) {
                    uint32_t b[4];
                    uint32_t boff = sw128((uint32_t)((n0 + np * 16 + (lane & 15)) * 128) + kb + koff);
                    ldm4(tB + boff, b);
                    mmaf16(acc[0][np * 2],     ah[0], b[0], b[2]);
                    mmaf16(acc[1][np * 2],     ah[1], b[0], b[2]);
                    mmaf16(acc[0][np * 2 + 1], ah[0], b[1], b[3]);
                    mmaf16(acc[1][np * 2 + 1], ah[1], b[1], b[3]);
                    mmaf16(acc[0][np * 2],     al[0], b[0], b[2]);
                    mmaf16(acc[1][np * 2],     al[1], b[0], b[2]);
                    mmaf16(acc[0][np * 2 + 1], al[0], b[1], b[3]);
                    mmaf16(acc[1][np * 2 + 1], al[1], b[1], b[3]);
                }
            }
        }
        __syncthreads();
        if (c < 14) SIM_LOAD(c + 2);
    }

    // token norms
#pragma unroll
    for (int g = 0; g < 8; ++g) {
        float s = ss[g];
        s += __shfl_xor_sync(0xffffffffu, s, 1);
        s += __shfl_xor_sync(0xffffffffu, s, 2);
        s += __shfl_xor_sync(0xffffffffu, s, 4);
        s += __shfl_xor_sync(0xffffffffu, s, 8);
        if (tx == 0) snorm[g * 16 + ty16] = s;
    }
    __syncthreads();   // all ldmatrix done before staging overwrites buffers

    // stage sim tile to smem (pitch SPITCH)
#pragma unroll
    for (int mt = 0; mt < 2; ++mt)
#pragma unroll
        for (int nt = 0; nt < 8; ++nt) {
            int r = m0 + mt * 16 + (lane >> 2);
            int col = n0 + nt * 8 + (lane & 3) * 2;
            *(float2*)&stage[r * SPITCH + col] = make_float2(acc[mt][nt][0], acc[mt][nt][1]);
            *(float2*)&stage[(r + 8) * SPITCH + col] = make_float2(acc[mt][nt][2], acc[mt][nt][3]);
        }
    __syncthreads();

    if (tid < 128) {
        float v[128];
#pragma unroll
        for (int j = 0; j < 128; ++j) v[j] = stage[tid * SPITCH + j];
        float sc = 10.0f / fmaxf(sqrtf(snorm[tid]), 1e-12f);  // (1/T)/max(||x||,eps)
        float mx = -1e30f;
#pragma unroll
        for (int j = 0; j < NE; ++j) { v[j] *= sc; mx = fmaxf(mx, v[j]); }
        float sum = 0.f;
#pragma unroll
        for (int j = 0; j < 128; ++j) {
            float t = (j < NE) ? __expf(v[j] - mx) : 0.f;
            v[j] = t;
            sum += t;
        }
        float inv = 1.0f / sum;
#pragma unroll
        for (int j = 0; j < 128; ++j) v[j] *= inv;

        size_t trow = row0 + tid;
        float* rp = aout + trow * NE;
#pragma unroll
        for (int j = 0; j < 25; ++j)
            *(float4*)(rp + j * 4) = make_float4(v[j * 4], v[j * 4 + 1], v[j * 4 + 2], v[j * 4 + 3]);
        // assignment^T fp16 for GEMM2 (warp-coalesced: lanes span consecutive tokens)
#pragma unroll
        for (int e = 0; e < 128; ++e)
            g_th_a[(size_t)e * BT + trow] = __float2half_rn(v[e]);
        // write back for weight column sums
#pragma unroll
        for (int j = 0; j < 128; ++j) stage[tid * SPITCH + j] = v[j];
    }
    __syncthreads();
    if (tid < 128) {
        float s = 0.f;
#pragma unroll
        for (int r = 0; r < 128; ++r) s += stage[r * SPITCH + tid];
        g_wpart[blockIdx.x * 128 + tid] = s;
    }
}

// ---------------- kernel 3: entity_features GEMM (fp16: asg x tokens hi/lo) -----------
// Single 48KB buffer: tA (asg, 16K), tBh (tokens hi, 16K), tBl (tokens lo, 16K); 2 CTA/SM.
#define EF_SMEM (1024 + 49152)

__global__ void __launch_bounds__(256, 2) k_ef(const float* __restrict__ tokens) {
    extern __shared__ char dsm[];
    uint32_t raw = smem_u32(dsm);
    uint32_t tiles = (raw + 1023u) & ~1023u;

    int tid = threadIdx.x;
    int lane = tid & 31, w = tid >> 5;
    int wm = w & 3, wn = w >> 2;
    int m0 = wm * 32, n0 = wn * 64;

    int bid = blockIdx.x;
    int dt = bid & 7;
    int b  = (bid >> 3) & 7;
    int s  = bid >> 6;             // 0..3
    size_t tok0 = (size_t)b * 4096 + (size_t)s * 1024;

    const int ty16 = tid >> 4, tx = tid & 15;
    const int brow = tid >> 3, q = tid & 7;

    float acc[2][8][4];
#pragma unroll
    for (int i = 0; i < 2; ++i)
#pragma unroll
        for (int j = 0; j < 8; ++j)
#pragma unroll
            for (int p = 0; p < 4; ++p) acc[i][j][p] = 0.f;

    uint32_t krow = (uint32_t)((lane & 7) + ((lane >> 4) & 1) * 8);
    uint32_t dh16 = (uint32_t)((lane >> 3) & 1) * 16u;
    uint32_t bsub = (uint32_t)wn * 8192u;

    for (int c = 0; c < 16; ++c) {
        uint32_t sA = tiles, sBh = tiles + 16384u, sBl = tiles + 32768u;
        // A: assignment^T fp16 [e][t]
#pragma unroll
        for (int p = 0; p < 4; ++p) {
            int r = p * 32 + brow;
            uint32_t off = sw128((uint32_t)(r * 128 + q * 16));
            sts128(sA + off, *(const uint4*)(g_th_a + (size_t)r * BT + tok0 + c * 64 + q * 8));
        }
        // B: tokens fp32 -> fp16 hi/lo, two 64x64 subtiles [k][d]
#pragma unroll
        for (int g = 0; g < 4; ++g)
#pragma unroll
            for (int sub = 0; sub < 2; ++sub) {
                float4 a = *(const float4*)(tokens + (tok0 + c * 64 + g * 16 + ty16) * DD +
                                            dt * 128 + sub * 64 + tx * 4);
                float h0 = __half2float(__float2half_rn(a.x));
                float h1 = __half2float(__float2half_rn(a.y));
                float h2 = __half2float(__float2half_rn(a.z));
                float h3 = __half2float(__float2half_rn(a.w));
                uint32_t off = (uint32_t)sub * 8192u +
                               sw128((uint32_t)((g * 16 + ty16) * 128 + tx * 8));
                sts64(sBh + off, pk_f16(h0, h1), pk_f16(h2, h3));
                sts64(sBl + off, pk_f16(a.x - h0, a.y - h1), pk_f16(a.z - h2, a.w - h3));
            }
        __syncthreads();
        // MMA phase: 2 terms (a*th, a*tl), 8 HMMAs per (ks,np)
        {
            uint32_t tA = tiles, tBh = tiles + 16384u, tBl = tiles + 32768u;
            uint32_t koff = (uint32_t)((lane >> 4) & 1) * 16u;
#pragma unroll
            for (int ks = 0; ks < 4; ++ks) {
                uint32_t kb = (uint32_t)ks * 32u;
                uint32_t a[2][4];
#pragma unroll
                for (int mt = 0; mt < 2; ++mt) {
                    uint32_t off = sw128((uint32_t)((m0 + mt * 16 + (lane & 15)) * 128) + kb + koff);
                    ldm4(tA + off, a[mt]);
                }
#pragma unroll
                for (int np = 0; np < 4; ++np) {
                    uint32_t bh[4], bl[4];
                    uint32_t boff = bsub + sw128((uint32_t)((ks * 16 + krow) * 128 + np * 32) + dh16);
                    ldm4t(tBh + boff, bh);
                    ldm4t(tBl + boff, bl);
                    mmaf16(acc[0][np * 2],     a[0], bh[0], bh[2]);
                    mmaf16(acc[1][np * 2],     a[1], bh[0], bh[2]);
                    mmaf16(acc[0][np * 2 + 1], a[0], bh[1], bh[3]);
                    mmaf16(acc[1][np * 2 + 1], a[1], bh[1], bh[3]);
                    mmaf16(acc[0][np * 2],     a[0], bl[0], bl[2]);
                    mmaf16(acc[1][np * 2],     a[1], bl[0], bl[2]);
                    mmaf16(acc[0][np * 2 + 1], a[0], bl[1], bl[3]);
                    mmaf16(acc[1][np * 2 + 1], a[1], bl[1], bl[3]);
                }
            }
        }
        __syncthreads();
    }

    float* ob = g_efpart + ((size_t)(s * 8 + b) * 128) * DD + (size_t)dt * 128;
#pragma unroll
    for (int mt = 0; mt < 2; ++mt)
#pragma unroll
        for (int nt = 0; nt < 8; ++nt) {
            int e = m0 + mt * 16 + (lane >> 2);
            int d = n0 + nt * 8 + (lane & 3) * 2;
            *(float2*)(ob + (size_t)e * DD + d) = make_float2(acc[mt][nt][0], acc[mt][nt][1]);
            *(float2*)(ob + (size_t)(e + 8) * DD + d) = make_float2(acc[mt][nt][2], acc[mt][nt][3]);
        }
}

// ---------------- kernel 4: combine 4 splits + inline weight reduce + divide ----------
__global__ void __launch_bounds__(256) k_combine(float* __restrict__ efout) {
    __shared__ float wsh;
    int be = blockIdx.x;           // b*100 + e
    int e = be % 100;
    int b = be / 100;
    int tid = threadIdx.x;

    if (tid < 32) {
        float s = g_wpart[(b * 32 + tid) * 128 + e];
#pragma unroll
        for (int m = 16; m; m >>= 1) s += __shfl_xor_sync(0xffffffffu, s, m);
        if (tid == 0) wsh = s + 1e-6f;
    }
    __syncthreads();
    float inv = 1.0f / wsh;

    int d4 = tid;
    const float4* p = (const float4*)g_efpart;
    size_t idx = ((size_t)b * 128 + e) * 256 + d4;
    size_t sstr = (size_t)8 * 128 * 256;
    float4 v = p[idx];
    float4 t;
    t = p[idx + sstr];     v.x += t.x; v.y += t.y; v.z += t.z; v.w += t.w;
    t = p[idx + 2 * sstr]; v.x += t.x; v.y += t.y; v.z += t.z; v.w += t.w;
    t = p[idx + 3 * sstr]; v.x += t.x; v.y += t.y; v.z += t.z; v.w += t.w;
    ((float4*)efout)[(size_t)be * 256 + d4] =
        make_float4(v.x * inv, v.y * inv, v.z * inv, v.w * inv);
}

extern "C" void kernel_launch(void* const* d_in, const int* in_sizes, int n_in,
                              void* d_out, int out_size) {
    const float* tokens = (const float*)d_in[0];   // (8,4096,1024)
    const float* cent   = (const float*)d_in[1];   // (100,1024)
    float* out = (float*)d_out;                    // assignment | entity_features

    cudaFuncSetAttribute(k_sim, cudaFuncAttributeMaxDynamicSharedMemorySize, SIM_SMEM);
    cudaFuncSetAttribute(k_ef,  cudaFuncAttributeMaxDynamicSharedMemorySize, EF_SMEM);

    k_cnorm<<<128, 256>>>(cent);
    k_sim<<<256, 256, SIM_SMEM>>>(tokens, out);
    k_ef<<<256, 256, EF_SMEM>>>(tokens);
    k_combine<<<800, 256>>>(out + (size_t)BT * NE);
}